// round 16
// baseline (speedup 1.0000x reference)
#include <cuda_runtime.h>

#define F_DIM 513
#define T_DIM 256
#define C_DIM 8
#define N_DIM 4
#define TF (T_DIM * F_DIM)        // 131328
#define NF (N_DIM * F_DIM)        // 2052
#define DIAG_LOAD 7.0710678118654755e-4f  // 0.001/sqrt(2)
#define GRID 136                   // 17 x 8 <= 148 SMs -> co-resident

// FINAL covariances (already /T): [input(2)][n(4)][entry(64)][f(513)]
__device__ float g_cov[2 * N_DIM * 64 * F_DIM];
// conj(W): [n][c][{re,im}][f]
__device__ float g_wc[N_DIM * C_DIM * 2 * F_DIM];
// grid barrier counter (monotonic across graph replays)
__device__ unsigned int g_bar;

// ---- packed fp32x2 helpers (FFMA2 is PTX-only) ----
__device__ __forceinline__ unsigned long long pack2(float lo, float hi) {
    unsigned long long r;
    asm("mov.b64 %0, {%1, %2};" : "=l"(r) : "f"(lo), "f"(hi));
    return r;
}
__device__ __forceinline__ void fma2(unsigned long long& acc,
                                     unsigned long long a, unsigned long long b) {
    asm("fma.rn.f32x2 %0, %1, %2, %0;" : "+l"(acc) : "l"(a), "l"(b));
}
__device__ __forceinline__ void unpack2(unsigned long long v, float& lo, float& hi) {
    asm("mov.b64 {%0, %1}, %2;" : "=f"(lo), "=f"(hi) : "l"(v));
}

__device__ __forceinline__ void grid_barrier() {
    __syncthreads();
    if (threadIdx.x == 0) {
        __threadfence();
        unsigned old = atomicAdd(&g_bar, 1u);
        unsigned target = (old / GRID + 1u) * GRID;
        while (*(volatile unsigned int*)&g_bar < target) __nanosleep(64);
        __threadfence();
    }
    __syncthreads();
}

// -------------------------------------------------------------------------
// Kernel 1: cov (R11 body) + grid barrier + fused solve. 136 x 512.
// -------------------------------------------------------------------------
__global__ __launch_bounds__(512, 1) void cov_solve_kernel(
    const float* __restrict__ target, const float* __restrict__ noise,
    const int* __restrict__ ref_idx)
{
    __shared__ float s_raw[16 * 16 * 32];   // 32 KB, reused across phases
    int tid = threadIdx.x;
    int bx  = blockIdx.x;

    // ===================== Phase 1: covariance =====================
    {
        int fb = bx % 17;
        int z  = bx / 17;
        int fx = tid & 31;
        int sl = tid >> 5;
        int gf = fb * 32 + fx;
        int fc = min(gf, F_DIM - 1);
        int inp = z & 1;
        int n   = z >> 1;
        const float* src = inp ? noise : target;
        int t0 = sl * 16;

        unsigned long long acc[28], dd[8];
#pragma unroll
        for (int k = 0; k < 28; k++) acc[k] = 0ull;
#pragma unroll
        for (int c = 0; c < 8; c++) dd[c] = 0ull;

        const float* base = src + (size_t)(16 * n) * TF + fc + (size_t)t0 * F_DIM;

#pragma unroll
        for (int tt = 0; tt < 16; ++tt) {
            const float* p = base + (size_t)tt * F_DIM;
            float x[16];
#pragma unroll
            for (int v = 0; v < 16; v++)
                x[v] = __ldg(p + (size_t)v * TF);

            unsigned long long P[8], Q[8];
#pragma unroll
            for (int c = 0; c < 8; c++) {
                P[c] = pack2(x[c], x[8 + c]);
                Q[c] = pack2(x[8 + c], -x[c]);
                fma2(dd[c], P[c], P[c]);
            }
#pragma unroll
            for (int j = 1; j < 8; j++) {
                unsigned long long BR = pack2(x[j], x[j]);
                unsigned long long BI = pack2(x[8 + j], x[8 + j]);
#pragma unroll
                for (int i = 0; i < j; i++) {
                    int kk = 7 * i - (i * (i - 1)) / 2 + (j - i - 1);
                    fma2(acc[kk], P[i], BR);
                    fma2(acc[kk], Q[i], BI);
                }
            }
        }

        float d[8], orr[28], oii[28];
#pragma unroll
        for (int c = 0; c < 8; c++) {
            float a, b; unpack2(dd[c], a, b); d[c] = a + b;
        }
#pragma unroll
        for (int k = 0; k < 28; k++) unpack2(acc[k], orr[k], oii[k]);

        float (*sred)[16][32] = (float(*)[16][32])s_raw;
        float* gout = g_cov + (size_t)(inp * N_DIM + n) * 64 * F_DIM;
        const float invT = 1.0f / (float)T_DIM;

#pragma unroll
        for (int b = 0; b < 4; b++) {
#pragma unroll
            for (int q = 0; q < 16; q++) {
                int e = b * 16 + q;
                float v = (e < 8) ? d[e] : (e < 36 ? orr[e - 8] : oii[e - 36]);
                sred[q][sl][fx] = v;
            }
            __syncthreads();
            {
                float sv = 0.f;
#pragma unroll
                for (int s = 0; s < 16; s++) sv += sred[sl][s][fx];
                if (gf < F_DIM)
                    gout[(size_t)(b * 16 + sl) * F_DIM + gf] = sv * invT;
            }
            __syncthreads();
        }
    }

    grid_barrier();

    // ===================== Phase 2: solve (16 matrices / block) ==============
    {
        int m0 = bx * 16;
        if (m0 < NF) {
            float (*s_cov)[64][17] = (float(*)[64][17])s_raw;  // [2][64][17]
#pragma unroll
            for (int r = 0; r < 4; r++) {
                int o  = r * 512 + tid;
                int mi = o & 15;
                int e  = (o >> 4) & 63;
                int ip = o >> 10;
                int m  = min(m0 + mi, NF - 1);
                int n  = m / F_DIM, f = m % F_DIM;
                s_cov[ip][e][mi] =
                    g_cov[((size_t)(ip * N_DIM + n) * 64 + e) * F_DIM + f];
            }
            __syncthreads();

            if (tid < 128) {
                int mi = tid >> 3;
                int i  = tid & 7;
                int m  = min(m0 + mi, NF - 1);
                int n  = m / F_DIM, f = m % F_DIM;
                const unsigned FULL = 0xffffffffu;

                float nr[8], ni[8];
#pragma unroll
                for (int j = 0; j < 8; j++) {
                    if (j == i) { nr[j] = s_cov[1][i][mi] + DIAG_LOAD; ni[j] = DIAG_LOAD; }
                    else {
                        int a = min(i, j), b = max(i, j);
                        int kk = 7 * a - (a * (a - 1)) / 2 + (b - a - 1);
                        float sign = (i < j) ? 1.f : -1.f;
                        nr[j] = s_cov[1][8 + kk][mi];
                        ni[j] = sign * s_cov[1][36 + kk][mi];
                    }
                }

#pragma unroll
                for (int kp = 0; kp < 8; kp++) {
                    float akk_r = __shfl_sync(FULL, nr[kp], kp, 8);
                    float akk_i = __shfl_sync(FULL, ni[kp], kp, 8);
                    float idn = 1.0f / fmaf(akk_r, akk_r, akk_i * akk_i);
                    float p_r = akk_r * idn, p_i = -akk_i * idn;
                    float s_r[8], s_i[8];
#pragma unroll
                    for (int j = 0; j < 8; j++) {
                        float ar = __shfl_sync(FULL, nr[j], kp, 8);
                        float ai = __shfl_sync(FULL, ni[j], kp, 8);
                        s_r[j] = ar * p_r - ai * p_i;
                        s_i[j] = ar * p_i + ai * p_r;
                    }
                    if (i == kp) {
#pragma unroll
                        for (int j = 0; j < 8; j++) { nr[j] = s_r[j]; ni[j] = s_i[j]; }
                        nr[kp] = p_r; ni[kp] = p_i;
                    } else {
                        float f_r = nr[kp], f_i = ni[kp];
#pragma unroll
                        for (int j = 0; j < 8; j++) {
                            if (j == kp) continue;
                            nr[j] -= f_r * s_r[j] - f_i * s_i[j];
                            ni[j] -= f_r * s_i[j] + f_i * s_r[j];
                        }
                        nr[kp] = -(f_r * p_r - f_i * p_i);
                        ni[kp] = -(f_r * p_i + f_i * p_r);
                    }
                }

                float tr_[8], ti[8];
#pragma unroll
                for (int j = 0; j < 8; j++) {
                    if (j == i) { tr_[j] = s_cov[0][i][mi]; ti[j] = 0.f; }
                    else {
                        int a = min(i, j), b = max(i, j);
                        int kk = 7 * a - (a * (a - 1)) / 2 + (b - a - 1);
                        float sign = (i < j) ? 1.f : -1.f;
                        tr_[j] = s_cov[0][8 + kk][mi];
                        ti[j]  = sign * s_cov[0][36 + kk][mi];
                    }
                }

                float trc_r = 0.f, trc_i = 0.f;
#pragma unroll
                for (int j = 0; j < 8; j++) {
                    trc_r += nr[j] * tr_[j] + ni[j] * ti[j];
                    trc_i += ni[j] * tr_[j] - nr[j] * ti[j];
                }
#pragma unroll
                for (int off = 4; off > 0; off >>= 1) {
                    trc_r += __shfl_xor_sync(FULL, trc_r, off, 8);
                    trc_i += __shfl_xor_sync(FULL, trc_i, off, 8);
                }

                int ref = *ref_idx;
                float pr = 0.f, pi = 0.f;
#pragma unroll
                for (int jj = 0; jj < 8; jj++)
                    if (jj == ref) { pr = tr_[jj]; pi = ti[jj]; }

                float w_r = 0.f, w_i = 0.f;
#pragma unroll
                for (int j = 0; j < 8; j++) {
                    float br = __shfl_sync(FULL, pr, j, 8);
                    float bi = __shfl_sync(FULL, pi, j, 8);
                    w_r += nr[j] * br - ni[j] * bi;
                    w_i += nr[j] * bi + ni[j] * br;
                }

                float ldn = 1.0f / fmaf(trc_r, trc_r, trc_i * trc_i);
                float lr = trc_r * ldn, li = -trc_i * ldn;
                float Wr = w_r * lr - w_i * li;
                float Wi = w_r * li + w_i * lr;

                g_wc[((n * 8 + i) * 2 + 0) * F_DIM + f] = Wr;
                g_wc[((n * 8 + i) * 2 + 1) * F_DIM + f] = -Wi;
            }
        }
    }
}

// -------------------------------------------------------------------------
// Kernel 2: beamform, W-amortized. Block (128 f, 2 halves), grid (5, 32, 4)
// = 640 blocks. Each thread: one f, 4 t's (2 iterations x 2-t batch).
// W loaded ONCE per thread (16 LDG), y loads 32-deep per iteration.
// -------------------------------------------------------------------------
__global__ __launch_bounds__(256) void beamform_kernel(
    const float* __restrict__ mix, float* __restrict__ out)
{
    int f = blockIdx.x * 128 + (threadIdx.x & 127);
    if (f >= F_DIM) return;
    int half = threadIdx.x >> 7;            // 0..1
    int n  = blockIdx.z;
    int tb = blockIdx.y * 8 + half * 4;     // this thread's 4 t's

    float wr[8], wi[8];
#pragma unroll
    for (int c = 0; c < 8; c++) {
        wr[c] = g_wc[((n * 8 + c) * 2 + 0) * F_DIM + f];
        wi[c] = g_wc[((n * 8 + c) * 2 + 1) * F_DIM + f];
    }

    const float* baseR = mix + (size_t)(16 * n) * TF + f;
    const float* baseI = mix + (size_t)(16 * n + 8) * TF + f;
    float* outR = out + (size_t)(2 * n) * TF + f;      // (N,2,1,T,F)
    float* outI = out + (size_t)(2 * n + 1) * TF + f;

#pragma unroll
    for (int it = 0; it < 2; it++) {
        int t0 = tb + it * 2;
        float yr[2][8], yi[2][8];
#pragma unroll
        for (int dt = 0; dt < 2; dt++) {
            int off = (t0 + dt) * F_DIM;
#pragma unroll
            for (int c = 0; c < 8; c++) {
                yr[dt][c] = __ldg(baseR + (size_t)c * TF + off);
                yi[dt][c] = __ldg(baseI + (size_t)c * TF + off);
            }
        }
#pragma unroll
        for (int dt = 0; dt < 2; dt++) {
            float Xr = 0.f, Xi = 0.f;
#pragma unroll
            for (int c = 0; c < 8; c++) {
                Xr += wr[c] * yr[dt][c] - wi[c] * yi[dt][c];
                Xi += wr[c] * yi[dt][c] + wi[c] * yr[dt][c];
            }
            int off = (t0 + dt) * F_DIM;
            outR[off] = Xr;
            outI[off] = Xi;
        }
    }
}

// -------------------------------------------------------------------------
extern "C" void kernel_launch(void* const* d_in, const int* in_sizes, int n_in,
                              void* d_out, int out_size)
{
    const float* mixture = (const float*)d_in[0];
    const float* target  = (const float*)d_in[1];
    const float* noise   = (const float*)d_in[2];
    const int*   ref     = (const int*)d_in[3];
    float* out = (float*)d_out;

    dim3 g1(GRID);                            // 136 blocks, co-resident
    cov_solve_kernel<<<g1, 512>>>(target, noise, ref);

    dim3 g3((F_DIM + 127) / 128, T_DIM / 8, N_DIM);   // 5 x 32 x 4 = 640
    beamform_kernel<<<g3, 256>>>(mixture, out);
}

// round 17
// speedup vs baseline: 1.2267x; 1.2267x over previous
#include <cuda_runtime.h>

#define F_DIM 513
#define T_DIM 256
#define C_DIM 8
#define N_DIM 4
#define TF (T_DIM * F_DIM)        // 131328
#define NF (N_DIM * F_DIM)        // 2052
#define DIAG_LOAD 7.0710678118654755e-4f  // 0.001/sqrt(2)
#define GRID 136                   // 17 x 8 <= 148 SMs -> co-resident

// FINAL covariances (already /T): [input(2)][n(4)][entry(64)][f(513)]
__device__ float g_cov[2 * N_DIM * 64 * F_DIM];
// conj(W): [n][c][{re,im}][f]
__device__ float g_wc[N_DIM * C_DIM * 2 * F_DIM];
// grid barrier counter (monotonic across graph replays)
__device__ unsigned int g_bar;

// ---- packed fp32x2 helpers (FFMA2 is PTX-only) ----
__device__ __forceinline__ unsigned long long pack2(float lo, float hi) {
    unsigned long long r;
    asm("mov.b64 %0, {%1, %2};" : "=l"(r) : "f"(lo), "f"(hi));
    return r;
}
__device__ __forceinline__ void fma2(unsigned long long& acc,
                                     unsigned long long a, unsigned long long b) {
    asm("fma.rn.f32x2 %0, %1, %2, %0;" : "+l"(acc) : "l"(a), "l"(b));
}
__device__ __forceinline__ void unpack2(unsigned long long v, float& lo, float& hi) {
    asm("mov.b64 {%0, %1}, %2;" : "=f"(lo), "=f"(hi) : "l"(v));
}

__device__ __forceinline__ void grid_barrier() {
    __syncthreads();
    if (threadIdx.x == 0) {
        __threadfence();
        unsigned old = atomicAdd(&g_bar, 1u);
        unsigned target = (old / GRID + 1u) * GRID;
        while (*(volatile unsigned int*)&g_bar < target) __nanosleep(64);
        __threadfence();
    }
    __syncthreads();
}

// -------------------------------------------------------------------------
// Kernel 1: cov (R11 body) + grid barrier + fused solve. 136 x 512.
// -------------------------------------------------------------------------
__global__ __launch_bounds__(512, 1) void cov_solve_kernel(
    const float* __restrict__ target, const float* __restrict__ noise,
    const int* __restrict__ ref_idx)
{
    __shared__ float s_raw[16 * 16 * 32];   // 32 KB, reused across phases
    int tid = threadIdx.x;
    int bx  = blockIdx.x;

    // ===================== Phase 1: covariance =====================
    {
        int fb = bx % 17;
        int z  = bx / 17;
        int fx = tid & 31;
        int sl = tid >> 5;
        int gf = fb * 32 + fx;
        int fc = min(gf, F_DIM - 1);
        int inp = z & 1;
        int n   = z >> 1;
        const float* src = inp ? noise : target;
        int t0 = sl * 16;

        unsigned long long acc[28], dd[8];
#pragma unroll
        for (int k = 0; k < 28; k++) acc[k] = 0ull;
#pragma unroll
        for (int c = 0; c < 8; c++) dd[c] = 0ull;

        const float* base = src + (size_t)(16 * n) * TF + fc + (size_t)t0 * F_DIM;

#pragma unroll
        for (int tt = 0; tt < 16; ++tt) {
            const float* p = base + (size_t)tt * F_DIM;
            float x[16];
#pragma unroll
            for (int v = 0; v < 16; v++)
                x[v] = __ldg(p + (size_t)v * TF);

            unsigned long long P[8], Q[8];
#pragma unroll
            for (int c = 0; c < 8; c++) {
                P[c] = pack2(x[c], x[8 + c]);
                Q[c] = pack2(x[8 + c], -x[c]);
                fma2(dd[c], P[c], P[c]);
            }
#pragma unroll
            for (int j = 1; j < 8; j++) {
                unsigned long long BR = pack2(x[j], x[j]);
                unsigned long long BI = pack2(x[8 + j], x[8 + j]);
#pragma unroll
                for (int i = 0; i < j; i++) {
                    int kk = 7 * i - (i * (i - 1)) / 2 + (j - i - 1);
                    fma2(acc[kk], P[i], BR);
                    fma2(acc[kk], Q[i], BI);
                }
            }
        }

        float d[8], orr[28], oii[28];
#pragma unroll
        for (int c = 0; c < 8; c++) {
            float a, b; unpack2(dd[c], a, b); d[c] = a + b;
        }
#pragma unroll
        for (int k = 0; k < 28; k++) unpack2(acc[k], orr[k], oii[k]);

        float (*sred)[16][32] = (float(*)[16][32])s_raw;
        float* gout = g_cov + (size_t)(inp * N_DIM + n) * 64 * F_DIM;
        const float invT = 1.0f / (float)T_DIM;

#pragma unroll
        for (int b = 0; b < 4; b++) {
#pragma unroll
            for (int q = 0; q < 16; q++) {
                int e = b * 16 + q;
                float v = (e < 8) ? d[e] : (e < 36 ? orr[e - 8] : oii[e - 36]);
                sred[q][sl][fx] = v;
            }
            __syncthreads();
            {
                float sv = 0.f;
#pragma unroll
                for (int s = 0; s < 16; s++) sv += sred[sl][s][fx];
                if (gf < F_DIM)
                    gout[(size_t)(b * 16 + sl) * F_DIM + gf] = sv * invT;
            }
            __syncthreads();
        }
    }

    grid_barrier();

    // ===================== Phase 2: solve (16 matrices / block) ==============
    {
        int m0 = bx * 16;
        if (m0 < NF) {
            float (*s_cov)[64][17] = (float(*)[64][17])s_raw;  // [2][64][17]
#pragma unroll
            for (int r = 0; r < 4; r++) {
                int o  = r * 512 + tid;
                int mi = o & 15;
                int e  = (o >> 4) & 63;
                int ip = o >> 10;
                int m  = min(m0 + mi, NF - 1);
                int n  = m / F_DIM, f = m % F_DIM;
                s_cov[ip][e][mi] =
                    g_cov[((size_t)(ip * N_DIM + n) * 64 + e) * F_DIM + f];
            }
            __syncthreads();

            if (tid < 128) {
                int mi = tid >> 3;
                int i  = tid & 7;
                int m  = min(m0 + mi, NF - 1);
                int n  = m / F_DIM, f = m % F_DIM;
                const unsigned FULL = 0xffffffffu;

                float nr[8], ni[8];
#pragma unroll
                for (int j = 0; j < 8; j++) {
                    if (j == i) { nr[j] = s_cov[1][i][mi] + DIAG_LOAD; ni[j] = DIAG_LOAD; }
                    else {
                        int a = min(i, j), b = max(i, j);
                        int kk = 7 * a - (a * (a - 1)) / 2 + (b - a - 1);
                        float sign = (i < j) ? 1.f : -1.f;
                        nr[j] = s_cov[1][8 + kk][mi];
                        ni[j] = sign * s_cov[1][36 + kk][mi];
                    }
                }

#pragma unroll
                for (int kp = 0; kp < 8; kp++) {
                    float akk_r = __shfl_sync(FULL, nr[kp], kp, 8);
                    float akk_i = __shfl_sync(FULL, ni[kp], kp, 8);
                    float idn = 1.0f / fmaf(akk_r, akk_r, akk_i * akk_i);
                    float p_r = akk_r * idn, p_i = -akk_i * idn;
                    float s_r[8], s_i[8];
#pragma unroll
                    for (int j = 0; j < 8; j++) {
                        float ar = __shfl_sync(FULL, nr[j], kp, 8);
                        float ai = __shfl_sync(FULL, ni[j], kp, 8);
                        s_r[j] = ar * p_r - ai * p_i;
                        s_i[j] = ar * p_i + ai * p_r;
                    }
                    if (i == kp) {
#pragma unroll
                        for (int j = 0; j < 8; j++) { nr[j] = s_r[j]; ni[j] = s_i[j]; }
                        nr[kp] = p_r; ni[kp] = p_i;
                    } else {
                        float f_r = nr[kp], f_i = ni[kp];
#pragma unroll
                        for (int j = 0; j < 8; j++) {
                            if (j == kp) continue;
                            nr[j] -= f_r * s_r[j] - f_i * s_i[j];
                            ni[j] -= f_r * s_i[j] + f_i * s_r[j];
                        }
                        nr[kp] = -(f_r * p_r - f_i * p_i);
                        ni[kp] = -(f_r * p_i + f_i * p_r);
                    }
                }

                float tr_[8], ti[8];
#pragma unroll
                for (int j = 0; j < 8; j++) {
                    if (j == i) { tr_[j] = s_cov[0][i][mi]; ti[j] = 0.f; }
                    else {
                        int a = min(i, j), b = max(i, j);
                        int kk = 7 * a - (a * (a - 1)) / 2 + (b - a - 1);
                        float sign = (i < j) ? 1.f : -1.f;
                        tr_[j] = s_cov[0][8 + kk][mi];
                        ti[j]  = sign * s_cov[0][36 + kk][mi];
                    }
                }

                float trc_r = 0.f, trc_i = 0.f;
#pragma unroll
                for (int j = 0; j < 8; j++) {
                    trc_r += nr[j] * tr_[j] + ni[j] * ti[j];
                    trc_i += ni[j] * tr_[j] - nr[j] * ti[j];
                }
#pragma unroll
                for (int off = 4; off > 0; off >>= 1) {
                    trc_r += __shfl_xor_sync(FULL, trc_r, off, 8);
                    trc_i += __shfl_xor_sync(FULL, trc_i, off, 8);
                }

                int ref = *ref_idx;
                float pr = 0.f, pi = 0.f;
#pragma unroll
                for (int jj = 0; jj < 8; jj++)
                    if (jj == ref) { pr = tr_[jj]; pi = ti[jj]; }

                float w_r = 0.f, w_i = 0.f;
#pragma unroll
                for (int j = 0; j < 8; j++) {
                    float br = __shfl_sync(FULL, pr, j, 8);
                    float bi = __shfl_sync(FULL, pi, j, 8);
                    w_r += nr[j] * br - ni[j] * bi;
                    w_i += nr[j] * bi + ni[j] * br;
                }

                float ldn = 1.0f / fmaf(trc_r, trc_r, trc_i * trc_i);
                float lr = trc_r * ldn, li = -trc_i * ldn;
                float Wr = w_r * lr - w_i * li;
                float Wi = w_r * li + w_i * lr;

                g_wc[((n * 8 + i) * 2 + 0) * F_DIM + f] = Wr;
                g_wc[((n * 8 + i) * 2 + 1) * F_DIM + f] = -Wi;
            }
        }
    }
}

// -------------------------------------------------------------------------
// Kernel 2: beamform (R15 shape: 2560 x 128, TPER=2) with the 32-load batch
// PINNED LIVE via empty asm so ptxas cannot sink/serialize the loads.
// __launch_bounds__(128, 8) permits 64 regs -> 8 blocks/SM, MLP=32/thread.
// -------------------------------------------------------------------------
#define TPER 2
__global__ __launch_bounds__(128, 8) void beamform_kernel(
    const float* __restrict__ mix, float* __restrict__ out)
{
    int f = blockIdx.x * blockDim.x + threadIdx.x;
    if (f >= F_DIM) return;
    int n  = blockIdx.z;
    int t0 = blockIdx.y * TPER;

    float wr[8], wi[8];
#pragma unroll
    for (int c = 0; c < 8; c++) {
        wr[c] = g_wc[((n * 8 + c) * 2 + 0) * F_DIM + f];
        wi[c] = g_wc[((n * 8 + c) * 2 + 1) * F_DIM + f];
    }

    const float* baseR = mix + (size_t)(16 * n) * TF + f;
    const float* baseI = mix + (size_t)(16 * n + 8) * TF + f;
    float* outR = out + (size_t)(2 * n) * TF + f;      // (N,2,1,T,F)
    float* outI = out + (size_t)(2 * n + 1) * TF + f;

    float yr[TPER][8], yi[TPER][8];
#pragma unroll
    for (int dt = 0; dt < TPER; dt++) {
        int off = (t0 + dt) * F_DIM;
#pragma unroll
        for (int c = 0; c < 8; c++) {
            yr[dt][c] = __ldg(baseR + (size_t)c * TF + off);
            yi[dt][c] = __ldg(baseI + (size_t)c * TF + off);
        }
    }
    // Pin all 32 loaded values live at this point: forces ptxas to batch
    // the 32 LDGs with results co-resident (MLP=32) instead of sinking them.
    asm volatile("" :
        "+f"(yr[0][0]), "+f"(yr[0][1]), "+f"(yr[0][2]), "+f"(yr[0][3]),
        "+f"(yr[0][4]), "+f"(yr[0][5]), "+f"(yr[0][6]), "+f"(yr[0][7]),
        "+f"(yr[1][0]), "+f"(yr[1][1]), "+f"(yr[1][2]), "+f"(yr[1][3]),
        "+f"(yr[1][4]), "+f"(yr[1][5]), "+f"(yr[1][6]), "+f"(yr[1][7]));
    asm volatile("" :
        "+f"(yi[0][0]), "+f"(yi[0][1]), "+f"(yi[0][2]), "+f"(yi[0][3]),
        "+f"(yi[0][4]), "+f"(yi[0][5]), "+f"(yi[0][6]), "+f"(yi[0][7]),
        "+f"(yi[1][0]), "+f"(yi[1][1]), "+f"(yi[1][2]), "+f"(yi[1][3]),
        "+f"(yi[1][4]), "+f"(yi[1][5]), "+f"(yi[1][6]), "+f"(yi[1][7]));

#pragma unroll
    for (int dt = 0; dt < TPER; dt++) {
        float Xr = 0.f, Xi = 0.f;
#pragma unroll
        for (int c = 0; c < 8; c++) {
            Xr += wr[c] * yr[dt][c] - wi[c] * yi[dt][c];
            Xi += wr[c] * yi[dt][c] + wi[c] * yr[dt][c];
        }
        int off = (t0 + dt) * F_DIM;
        outR[off] = Xr;
        outI[off] = Xi;
    }
}

// -------------------------------------------------------------------------
extern "C" void kernel_launch(void* const* d_in, const int* in_sizes, int n_in,
                              void* d_out, int out_size)
{
    const float* mixture = (const float*)d_in[0];
    const float* target  = (const float*)d_in[1];
    const float* noise   = (const float*)d_in[2];
    const int*   ref     = (const int*)d_in[3];
    float* out = (float*)d_out;

    dim3 g1(GRID);                            // 136 blocks, co-resident
    cov_solve_kernel<<<g1, 512>>>(target, noise, ref);

    dim3 g3((F_DIM + 127) / 128, T_DIM / TPER, N_DIM);   // 5 x 128 x 4 = 2560
    beamform_kernel<<<g3, 128>>>(mixture, out);
}